// round 13
// baseline (speedup 1.0000x reference)
#include <cuda_runtime.h>
#include <cuda_bf16.h>
#include <cstdint>

// Capsule routing: B=2048, R=64, H=512, NUM_ITER=3.  Output final_vec [B,H] f32.
//
// R12 = R11 structure + Blackwell packed-f32x2 softmax loops:
//  - fma.rn.f32x2 / add.rn.f32x2 halve FMA-pipe instruction count in both
//    softmax loops (softmax2 was issue-saturated at 8 instr/r = 32/32 slots
//    per MUFU window; now ~6 instr/r).
//  - xr kept as 32 packed f32x2 register pairs.
//  - sqrt.approx in squash.
// 148 persistent CTAs x 512 threads; TMA 7-slot x 32KB ring; 2 barriers/batch;
// deferred norm2+output into next softmax1 window (from R11).

#define B_DIM 2048
#define R_DIM 64
#define H_DIM 512
#define NT 512
#define GRID 148
#define NSLOT 7
#define CHUNK_ROWS 16
#define CHUNK_FLOATS (CHUNK_ROWS * H_DIM)      // 8192
#define CHUNK_BYTES  (CHUNK_FLOATS * 4)        // 32768
#define NPAIR 32

__device__ __forceinline__ float fast_exp2(float x) {
    float r;
    asm("ex2.approx.ftz.f32 %0, %1;" : "=f"(r) : "f"(x));
    return r;
}
__device__ __forceinline__ float fast_sqrt(float x) {
    float r;
    asm("sqrt.approx.f32 %0, %1;" : "=f"(r) : "f"(x));
    return r;
}

#define FMA2(d, a, b, c) \
    asm("fma.rn.f32x2 %0, %1, %2, %3;" : "=l"(d) : "l"(a), "l"(b), "l"(c))
#define ADD2(d, a, b) \
    asm("add.rn.f32x2 %0, %1, %2;" : "=l"(d) : "l"(a), "l"(b))
#define PACK2(d, lo, hi) \
    asm("mov.b64 %0, {%1, %2};" : "=l"(d) : "f"(lo), "f"(hi))
#define UNPACK2(lo, hi, s) \
    asm("mov.b64 {%0, %1}, %2;" : "=f"(lo), "=f"(hi) : "l"(s))

__device__ __forceinline__ void mbar_wait_acq(uint32_t mbar, uint32_t parity) {
    asm volatile(
        "{\n\t"
        ".reg .pred P;\n\t"
        "WAIT_LOOP_%=:\n\t"
        "mbarrier.try_wait.parity.acquire.cta.shared::cta.b64 P, [%0], %1, 0x989680;\n\t"
        "@P bra.uni WAIT_DONE_%=;\n\t"
        "bra.uni WAIT_LOOP_%=;\n\t"
        "WAIT_DONE_%=:\n\t"
        "}"
        :: "r"(mbar), "r"(parity) : "memory");
}

__device__ __forceinline__ void warp_part(float val, volatile float* sred,
                                          int wid, int lid) {
    #pragma unroll
    for (int o = 16; o > 0; o >>= 1)
        val += __shfl_xor_sync(0xffffffffu, val, o);
    if (lid == 0) sred[wid] = val;
}

__device__ __forceinline__ float final_sum(volatile float* sred, int lid) {
    float v = sred[lid & 15];
    #pragma unroll
    for (int o = 8; o > 0; o >>= 1)
        v += __shfl_xor_sync(0xffffffffu, v, o);
    return v;
}

__global__ void __launch_bounds__(NT, 1)
capsule_kernel(const float* __restrict__ x, float* __restrict__ out) {
    extern __shared__ float sbuf[];            // NSLOT * 32KB = 224KB ring
    __shared__ float sred0[16], sred1[16], sred2[16], sred3[16];
    __shared__ uint64_t mbars[NSLOT];

    const uint32_t mbar0 = (uint32_t)__cvta_generic_to_shared(mbars);
    const uint32_t sbuf_addr = (uint32_t)__cvta_generic_to_shared(sbuf);

    const int tid = threadIdx.x;               // == h column
    const int bid = blockIdx.x;
    const int wid = tid >> 5;
    const int lid = tid & 31;

    if (tid < NSLOT)
        asm volatile("mbarrier.init.shared.b64 [%0], %1;"
                     :: "r"(mbar0 + 8u * tid), "r"(1));
    asm volatile("fence.proxy.async.shared::cta;" ::: "memory");
    __syncthreads();

    const int nbat = (B_DIM - bid + GRID - 1) / GRID;
    const int total_chunks = 4 * nbat;

    auto issue = [&](int g) {
        int slot = g % NSLOT;
        int gb = bid + (g >> 2) * GRID;
        const char* src = (const char*)(x + (size_t)gb * (R_DIM * H_DIM)
                                          + (size_t)(g & 3) * CHUNK_FLOATS);
        uint32_t mb = mbar0 + 8u * slot;
        asm volatile("mbarrier.arrive.expect_tx.shared.b64 _, [%0], %1;"
                     :: "r"(mb), "r"(CHUNK_BYTES));
        asm volatile(
            "cp.async.bulk.shared::cta.global.mbarrier::complete_tx::bytes "
            "[%0], [%1], %2, [%3];"
            :: "r"(sbuf_addr + (uint32_t)slot * CHUNK_BYTES), "l"(src),
               "r"(CHUNK_BYTES), "r"(mb) : "memory");
    };

    int cursor = 0;
    if (tid == 0) {
        int lim = total_chunks < NSLOT ? total_chunks : NSLOT;
        for (; cursor < lim; cursor++) issue(cursor);
    }

    const float L2E = 1.4426950408889634f;

    // ================= prologue: batch 0 =================
    if (tid < 4)
        mbar_wait_acq(mbar0 + 8u * tid, 0u);
    __syncthreads();

    uint64_t xr2[NPAIR];                       // 32 packed row-pairs
    float sum0 = 0.0f, absmax = 0.0f;
    #pragma unroll
    for (int i = 0; i < NPAIR; i++) {
        int c = i >> 3;                        // chunk (8 pairs per 16-row chunk)
        int rr = (2 * i) & 15;                 // row within chunk
        const float* cp = sbuf + (size_t)c * CHUNK_FLOATS + tid;
        float x0 = cp[rr * H_DIM];
        float x1 = cp[(rr + 1) * H_DIM];
        PACK2(xr2[i], x0, x1);
        sum0 += x0 + x1;
        absmax = fmaxf(absmax, fabsf(x0));
        absmax = fmaxf(absmax, fabsf(x1));
    }
    float s0p = sum0 * (1.0f / (float)R_DIM);
    warp_part(s0p * s0p, sred0, wid, lid);
    __syncthreads();                           // batch 0 consumed
    if (tid == 0) {
        int lim = total_chunks - 1 < 10 ? total_chunks - 1 : 10;
        for (; cursor <= lim; cursor++) issue(cursor);
    }
    float w;
    {
        float sq = fast_sqrt(final_sum(sred0, lid));
        w = __fdividef(sq, 1.0f + sq) * s0p;    // v1 of batch 0
    }

    float s2_prev = 0.0f;
    int   b_prev  = -1;

    // ================= steady loop =================
    for (int i = 0; i < nbat; i++) {
        const int b = bid + i * GRID;
        const bool hn = (i + 1 < nbat);

        // ---- softmax1(i): packed f32x2, pure MUFU ----
        float wl = w * L2E;
        float m  = fabsf(wl) * absmax;
        uint64_t wl2, nm2, se2, sex2;
        PACK2(wl2, wl, wl);
        PACK2(nm2, -m, -m);
        PACK2(se2, 0.0f, 0.0f);
        PACK2(sex2, 0.0f, 0.0f);
        #pragma unroll
        for (int p = 0; p < NPAIR; p++) {
            uint64_t xp = xr2[p];
            uint64_t arg;
            FMA2(arg, xp, wl2, nm2);
            float a0, a1;
            UNPACK2(a0, a1, arg);
            float e0 = fast_exp2(a0);
            float e1 = fast_exp2(a1);
            uint64_t ep;
            PACK2(ep, e0, e1);
            ADD2(se2, se2, ep);
            FMA2(sex2, ep, xp, sex2);
        }
        float seA, seB, sxA, sxB;
        UNPACK2(seA, seB, se2);
        UNPACK2(sxA, sxB, sex2);
        float s1 = __fdividef(sxA + sxB, seA + seB);

        // ---- deferred: batch i-1's norm2 + output store ----
        if (b_prev >= 0) {
            float sq2 = fast_sqrt(final_sum(sred2, lid));
            out[(size_t)b_prev * H_DIM + tid] =
                __fdividef(sq2, 1.0f + sq2) * s2_prev;
        }

        // elected waits for batch i+1, folded into B1
        if (hn && tid < 4) {
            int g = 4 * (i + 1) + tid;
            mbar_wait_acq(mbar0 + 8u * (g % NSLOT),
                          (uint32_t)((g / NSLOT) & 1));
        }
        warp_part(s1 * s1, sred1, wid, lid);
        __syncthreads();                       // B1
        {
            float sq = fast_sqrt(final_sum(sred1, lid));
            w += __fdividef(sq, 1.0f + sq) * s1;
        }

        // next-batch chunk base pointers (clamped for last batch)
        const float* np[4];
        #pragma unroll
        for (int c = 0; c < 4; c++) {
            int g = 4 * (i + 1) + c;
            if (g > total_chunks - 1) g = total_chunks - 1;
            np[c] = sbuf + (size_t)(g % NSLOT) * CHUNK_FLOATS + tid;
        }

        // ---- softmax2(i): packed MUFU + in-place reload of i+1 + stats ----
        wl = w * L2E;
        m  = fabsf(wl) * absmax;
        PACK2(wl2, wl, wl);
        PACK2(nm2, -m, -m);
        PACK2(se2, 0.0f, 0.0f);
        PACK2(sex2, 0.0f, 0.0f);
        uint64_t nsum2;
        PACK2(nsum2, 0.0f, 0.0f);
        float namax = 0.0f;
        #pragma unroll
        for (int p = 0; p < NPAIR; p++) {
            uint64_t xp = xr2[p];
            uint64_t arg;
            FMA2(arg, xp, wl2, nm2);
            float a0, a1;
            UNPACK2(a0, a1, arg);
            float e0 = fast_exp2(a0);
            float e1 = fast_exp2(a1);
            uint64_t ep;
            PACK2(ep, e0, e1);
            ADD2(se2, se2, ep);
            FMA2(sex2, ep, xp, sex2);
            // reload pair from batch i+1 (same chunk for both rows)
            const float* cp = np[p >> 3];
            int rr = (2 * p) & 15;
            float x0 = cp[rr * H_DIM];
            float x1 = cp[(rr + 1) * H_DIM];
            uint64_t nx;
            PACK2(nx, x0, x1);
            xr2[p] = nx;
            ADD2(nsum2, nsum2, nx);
            namax = fmaxf(namax, fabsf(x0));
            namax = fmaxf(namax, fabsf(x1));
        }
        UNPACK2(seA, seB, se2);
        UNPACK2(sxA, sxB, sex2);
        float s2 = __fdividef(sxA + sxB, seA + seB);
        float n0, n1;
        UNPACK2(n0, n1, nsum2);
        float s0 = (n0 + n1) * (1.0f / (float)R_DIM);

        // ---- B2: partial reductions + refill ----
        warp_part(s2 * s2, sred2, wid, lid);
        warp_part(s0 * s0, sred3, wid, lid);
        __syncthreads();                       // B2 (batch i+1 consumed)
        if (tid == 0) {
            int lim = 4 * i + 14;
            if (lim > total_chunks - 1) lim = total_chunks - 1;
            for (; cursor <= lim; cursor++) issue(cursor);
        }
        if (hn) {
            float sq0 = fast_sqrt(final_sum(sred3, lid));
            w = __fdividef(sq0, 1.0f + sq0) * s0;   // v1 of batch i+1
            absmax = namax;
        }
        s2_prev = s2;
        b_prev  = b;
    }

    // ---- epilogue: flush last batch's output ----
    {
        float sq2 = fast_sqrt(final_sum(sred2, lid));
        out[(size_t)b_prev * H_DIM + tid] =
            __fdividef(sq2, 1.0f + sq2) * s2_prev;
    }
}

extern "C" void kernel_launch(void* const* d_in, const int* in_sizes, int n_in,
                              void* d_out, int out_size) {
    const float* x = (const float*)d_in[0];
    float* out = (float*)d_out;
    cudaFuncSetAttribute(capsule_kernel,
                         cudaFuncAttributeMaxDynamicSharedMemorySize,
                         NSLOT * CHUNK_BYTES);
    capsule_kernel<<<GRID, NT, NSLOT * CHUNK_BYTES>>>(x, out);
}

// round 15
// speedup vs baseline: 1.0006x; 1.0006x over previous
#include <cuda_runtime.h>
#include <cuda_bf16.h>
#include <cstdint>

// Capsule routing: B=2048, R=64, H=512, NUM_ITER=3.  Output final_vec [B,H] f32.
//
// R14 = R11 scalar body + deadline-spread TMA ring:
//  - 14 slots x 16KB chunks (224KB smem), 8 chunks per batch.
//  - refill at BOTH B1 and B2: first-needed chunks get a FULL period of
//    lead (was 0.5 period with 7x32KB + B2-only refill -> demand bursts,
//    B1 waits, DRAM duty stuck at ~64%).
//  - deferred norm2+output into next softmax1 window; __fdividef; approx sqrt.
// 148 persistent CTAs x 512 threads, thread = full h-column (xr[64]).

#define B_DIM 2048
#define R_DIM 64
#define H_DIM 512
#define NT 512
#define GRID 148
#define NSLOT 14
#define CPB 8                                  // chunks per batch
#define CHUNK_ROWS 8
#define CHUNK_FLOATS (CHUNK_ROWS * H_DIM)      // 4096
#define CHUNK_BYTES  (CHUNK_FLOATS * 4)        // 16384

__device__ __forceinline__ float fast_exp2(float x) {
    float r;
    asm("ex2.approx.ftz.f32 %0, %1;" : "=f"(r) : "f"(x));
    return r;
}
__device__ __forceinline__ float fast_sqrt(float x) {
    float r;
    asm("sqrt.approx.f32 %0, %1;" : "=f"(r) : "f"(x));
    return r;
}

__device__ __forceinline__ void mbar_wait_acq(uint32_t mbar, uint32_t parity) {
    asm volatile(
        "{\n\t"
        ".reg .pred P;\n\t"
        "WAIT_LOOP_%=:\n\t"
        "mbarrier.try_wait.parity.acquire.cta.shared::cta.b64 P, [%0], %1, 0x989680;\n\t"
        "@P bra.uni WAIT_DONE_%=;\n\t"
        "bra.uni WAIT_LOOP_%=;\n\t"
        "WAIT_DONE_%=:\n\t"
        "}"
        :: "r"(mbar), "r"(parity) : "memory");
}

// Warp partial sum -> sred[wid] (call before a __syncthreads()).
__device__ __forceinline__ void warp_part(float val, volatile float* sred,
                                          int wid, int lid) {
    #pragma unroll
    for (int o = 16; o > 0; o >>= 1)
        val += __shfl_xor_sync(0xffffffffu, val, o);
    if (lid == 0) sred[wid] = val;
}

// After the barrier: combine the 16 partials (all threads get the result).
__device__ __forceinline__ float final_sum(volatile float* sred, int lid) {
    float v = sred[lid & 15];
    #pragma unroll
    for (int o = 8; o > 0; o >>= 1)
        v += __shfl_xor_sync(0xffffffffu, v, o);
    return v;
}

__global__ void __launch_bounds__(NT, 1)
capsule_kernel(const float* __restrict__ x, float* __restrict__ out) {
    extern __shared__ float sbuf[];            // NSLOT * 16KB = 224KB ring
    __shared__ float sred1[16], sred2[16], sred3[16];
    __shared__ uint64_t mbars[NSLOT];

    const uint32_t mbar0 = (uint32_t)__cvta_generic_to_shared(mbars);
    const uint32_t sbuf_addr = (uint32_t)__cvta_generic_to_shared(sbuf);

    const int tid = threadIdx.x;               // == h column
    const int bid = blockIdx.x;
    const int wid = tid >> 5;
    const int lid = tid & 31;

    if (tid < NSLOT)
        asm volatile("mbarrier.init.shared.b64 [%0], %1;"
                     :: "r"(mbar0 + 8u * tid), "r"(1));
    asm volatile("fence.proxy.async.shared::cta;" ::: "memory");
    __syncthreads();

    const int nbat = (B_DIM - bid + GRID - 1) / GRID;
    const int total_chunks = CPB * nbat;

    auto issue = [&](int g) {
        int slot = g % NSLOT;
        int gb = bid + (g >> 3) * GRID;
        const char* src = (const char*)(x + (size_t)gb * (R_DIM * H_DIM)
                                          + (size_t)(g & 7) * CHUNK_FLOATS);
        uint32_t mb = mbar0 + 8u * slot;
        asm volatile("mbarrier.arrive.expect_tx.shared.b64 _, [%0], %1;"
                     :: "r"(mb), "r"(CHUNK_BYTES));
        asm volatile(
            "cp.async.bulk.shared::cta.global.mbarrier::complete_tx::bytes "
            "[%0], [%1], %2, [%3];"
            :: "r"(sbuf_addr + (uint32_t)slot * CHUNK_BYTES), "l"(src),
               "r"(CHUNK_BYTES), "r"(mb) : "memory");
    };

    int cursor = 0;
    if (tid == 0) {
        int lim = total_chunks < NSLOT ? total_chunks : NSLOT;
        for (; cursor < lim; cursor++) issue(cursor);
    }

    const float L2E = 1.4426950408889634f;

    // ================= prologue: batch 0 =================
    if (tid < CPB)
        mbar_wait_acq(mbar0 + 8u * tid, 0u);
    __syncthreads();

    float xr[R_DIM];
    float sum0 = 0.0f, absmax = 0.0f;
    #pragma unroll
    for (int c = 0; c < CPB; c++) {
        const float* cp = sbuf + (size_t)c * CHUNK_FLOATS + tid;
        #pragma unroll
        for (int r = 0; r < CHUNK_ROWS; r++) {
            float xv = cp[r * H_DIM];
            xr[c * CHUNK_ROWS + r] = xv;
            sum0 += xv;
            absmax = fmaxf(absmax, fabsf(xv));
        }
    }
    float s0p = sum0 * (1.0f / (float)R_DIM);
    warp_part(s0p * s0p, sred3, wid, lid);
    __syncthreads();                           // batch 0 consumed
    if (tid == 0) {                            // slots up to chunk 21 free
        int lim = total_chunks - 1 < CPB - 1 + NSLOT ? total_chunks - 1
                                                     : CPB - 1 + NSLOT;
        for (; cursor <= lim; cursor++) issue(cursor);
    }
    float w;
    {
        float sq = fast_sqrt(final_sum(sred3, lid));
        w = __fdividef(sq, 1.0f + sq) * s0p;    // v1 of batch 0
    }

    float s2_prev = 0.0f;
    int   b_prev  = -1;

    // ================= steady loop =================
    for (int i = 0; i < nbat; i++) {
        const int b = bid + i * GRID;
        const bool hn = (i + 1 < nbat);

        // ---- softmax1(i): pure MUFU ----
        float wl = w * L2E;
        float m  = fabsf(wl) * absmax;
        float se = 0.0f, sex = 0.0f;
        #pragma unroll
        for (int r = 0; r < R_DIM; r++) {
            float e = fast_exp2(fmaf(xr[r], wl, -m));
            se += e;
            sex = fmaf(e, xr[r], sex);
        }
        float s1 = __fdividef(sex, se);

        // ---- deferred: batch i-1's norm2 + output store ----
        if (b_prev >= 0) {
            float sq2 = fast_sqrt(final_sum(sred2, lid));
            out[(size_t)b_prev * H_DIM + tid] =
                __fdividef(sq2, 1.0f + sq2) * s2_prev;
        }

        // elected waits for batch i+1's 8 chunks, folded into B1
        if (hn && tid < CPB) {
            int g = CPB * (i + 1) + tid;
            mbar_wait_acq(mbar0 + 8u * (g % NSLOT),
                          (uint32_t)((g / NSLOT) & 1));
        }
        warp_part(s1 * s1, sred1, wid, lid);
        __syncthreads();                       // B1
        // refill #1: batches <= i consumed -> window up to 8i+7+14
        if (tid == 0) {
            int lim = CPB * i + CPB - 1 + NSLOT;
            if (lim > total_chunks - 1) lim = total_chunks - 1;
            for (; cursor <= lim; cursor++) issue(cursor);
        }
        {
            float sq = fast_sqrt(final_sum(sred1, lid));
            w += __fdividef(sq, 1.0f + sq) * s1;
        }

        // next-batch chunk base pointers (clamped for last batch)
        const float* np[CPB];
        #pragma unroll
        for (int c = 0; c < CPB; c++) {
            int g = CPB * (i + 1) + c;
            if (g > total_chunks - 1) g = total_chunks - 1;
            np[c] = sbuf + (size_t)(g % NSLOT) * CHUNK_FLOATS + tid;
        }

        // ---- softmax2(i): MUFU + in-place reload of batch i+1 + stats ----
        wl = w * L2E;
        m  = fabsf(wl) * absmax;
        float se2 = 0.0f, sex2 = 0.0f;
        float nsum = 0.0f, namax = 0.0f;
        #pragma unroll
        for (int r = 0; r < R_DIM; r++) {
            float xo = xr[r];
            float e = fast_exp2(fmaf(xo, wl, -m));
            se2 += e;
            sex2 = fmaf(e, xo, sex2);
            float xv = np[r >> 3][(r & 7) * H_DIM];
            xr[r] = xv;                        // xo dead after this r
            nsum += xv;
            namax = fmaxf(namax, fabsf(xv));
        }
        float s2 = __fdividef(sex2, se2);
        float s0 = nsum * (1.0f / (float)R_DIM);

        // ---- B2: partial reductions + refill #2 ----
        warp_part(s2 * s2, sred2, wid, lid);
        warp_part(s0 * s0, sred3, wid, lid);
        __syncthreads();                       // B2 (batch i+1 in regs)
        if (tid == 0) {
            int lim = CPB * (i + 1) + CPB - 1 + NSLOT;   // 8i+29
            if (lim > total_chunks - 1) lim = total_chunks - 1;
            for (; cursor <= lim; cursor++) issue(cursor);
        }
        if (hn) {
            float sq0 = fast_sqrt(final_sum(sred3, lid));
            w = __fdividef(sq0, 1.0f + sq0) * s0;   // v1 of batch i+1
            absmax = namax;
        }
        s2_prev = s2;
        b_prev  = b;
    }

    // ---- epilogue: flush last batch's output ----
    {
        float sq2 = fast_sqrt(final_sum(sred2, lid));
        out[(size_t)b_prev * H_DIM + tid] =
            __fdividef(sq2, 1.0f + sq2) * s2_prev;
    }
}

extern "C" void kernel_launch(void* const* d_in, const int* in_sizes, int n_in,
                              void* d_out, int out_size) {
    const float* x = (const float*)d_in[0];
    float* out = (float*)d_out;
    cudaFuncSetAttribute(capsule_kernel,
                         cudaFuncAttributeMaxDynamicSharedMemorySize,
                         NSLOT * CHUNK_BYTES);
    capsule_kernel<<<GRID, NT, NSLOT * CHUNK_BYTES>>>(x, out);
}